// round 15
// baseline (speedup 1.0000x reference)
#include <cuda_runtime.h>
#include <cuda_fp16.h>
#include <cstdint>

#define DN 128
#define N_MAX 100000
#define E_MAX 2000000
#define BPAD 136                 // padded fp16 row stride (ldmatrix conflict-free)

// ---------------------------------------------------------------------------
// Scratch (__device__ globals; no allocation allowed)
// ---------------------------------------------------------------------------
__device__ int   g_degi[N_MAX];
__device__ int   g_part[N_MAX];
__device__ int   g_bsums[512];
__device__ int   g_rowstart[N_MAX + 1];
__device__ int   g_cursor[N_MAX];
__device__ int   g_csr[E_MAX];
__device__ float g_dinv[N_MAX];
// fp16 feature buffers (dinv-scaled h / agg), 128 halfs per node
__device__ __align__(16) __half g_hbuf1[(size_t)N_MAX * DN];
__device__ __align__(16) __half g_hbuf2[(size_t)N_MAX * DN];
// W transposed: B[n][k] = W[k][n], fp16, padded [n][BPAD]; 2 layers
__device__ __align__(16) __half g_B[2][DN * BPAD];

__device__ __forceinline__ uint32_t smem_to_u32(const void* p) {
    uint32_t addr;
    asm("{ .reg .u64 tmp; cvta.to.shared.u64 tmp, %1; cvt.u32.u64 %0, tmp; }"
        : "=r"(addr) : "l"(p));
    return addr;
}

#define LDMATRIX_X4(r, addr) \
    asm volatile("ldmatrix.sync.aligned.m8n8.x4.shared.b16 {%0,%1,%2,%3}, [%4];" \
                 : "=r"((r)[0]), "=r"((r)[1]), "=r"((r)[2]), "=r"((r)[3]) \
                 : "r"(addr))

#define MMA_F16(d, a, b0, b1) \
    asm volatile("mma.sync.aligned.m16n8k16.row.col.f32.f16.f16.f32 " \
                 "{%0,%1,%2,%3}, {%4,%5,%6,%7}, {%8,%9}, {%0,%1,%2,%3};" \
                 : "+f"((d)[0]), "+f"((d)[1]), "+f"((d)[2]), "+f"((d)[3]) \
                 : "r"((a)[0]), "r"((a)[1]), "r"((a)[2]), "r"((a)[3]), \
                   "r"(b0), "r"(b1))

// ---------------------------------------------------------------------------
// CSR build (by target/col node) + dinv  — exact R10 structure
// ---------------------------------------------------------------------------
__global__ void k_count_deg(const int* __restrict__ col, int* __restrict__ deg, int e) {
    int i = blockIdx.x * blockDim.x + threadIdx.x;
    int base = i * 4;
    if (base + 3 < e) {
        int4 c = *reinterpret_cast<const int4*>(col + base);
        atomicAdd(&deg[c.x], 1);
        atomicAdd(&deg[c.y], 1);
        atomicAdd(&deg[c.z], 1);
        atomicAdd(&deg[c.w], 1);
    } else {
        for (int j = base; j < e; j++) atomicAdd(&deg[col[j]], 1);
    }
}

__global__ void k_scan1(const int* __restrict__ deg, int* __restrict__ part,
                        int* __restrict__ bsums, int n) {
    __shared__ int sh[256];
    int t = threadIdx.x;
    int i = blockIdx.x * 256 + t;
    int v = (i < n) ? deg[i] : 0;
    sh[t] = v;
    __syncthreads();
#pragma unroll
    for (int off = 1; off < 256; off <<= 1) {
        int add = (t >= off) ? sh[t - off] : 0;
        __syncthreads();
        sh[t] += add;
        __syncthreads();
    }
    if (i < n) part[i] = sh[t] - v;
    if (t == 255) bsums[blockIdx.x] = sh[255];
}

__global__ void k_scan3(const int* __restrict__ part, const int* __restrict__ bsums,
                        const int* __restrict__ deg, float* __restrict__ dinv,
                        int* __restrict__ rowstart, int* __restrict__ cursor,
                        int n, int e) {
    __shared__ int sred[256];
    int t = threadIdx.x;
    int accum = 0;
    for (int j = t; j < (int)blockIdx.x; j += 256) accum += bsums[j];
    sred[t] = accum;
    __syncthreads();
#pragma unroll
    for (int off = 128; off > 0; off >>= 1) {
        if (t < off) sred[t] += sred[t + off];
        __syncthreads();
    }
    int base = sred[0];

    int i = blockIdx.x * 256 + t;
    if (i < n) {
        int v = part[i] + base;
        rowstart[i] = v;
        cursor[i] = v;
        dinv[i] = rsqrtf((float)deg[i] + 1.0f);
    }
    if (i == 0 && blockIdx.x == 0) rowstart[n] = e;
}

__global__ void k_fill(const int* __restrict__ rowv, const int* __restrict__ colv,
                       int* __restrict__ cursor, int* __restrict__ csr, int e) {
    int i = blockIdx.x * blockDim.x + threadIdx.x;
    if (i < e) {
        int pos = atomicAdd(&cursor[colv[i]], 1);
        csr[pos] = rowv[i];
    }
}

__global__ void k_wconv(const float* __restrict__ W1, const float* __restrict__ W2,
                        __half* __restrict__ B) {
    int gi = blockIdx.x * blockDim.x + threadIdx.x;
    if (gi >= 2 * DN * DN) return;
    int layer = gi >> 14;
    int i = gi & (DN * DN - 1);
    const float* W = layer ? W2 : W1;
    int nrow = i & 127;
    int k = i >> 7;
    B[layer * DN * BPAD + nrow * BPAD + k] = __float2half_rn(W[k * DN + nrow]);
}

// ---------------------------------------------------------------------------
// mma.sync GEMM: C_fp16[i,:] = dinv[i] * (act(A[i,:]) @ W)
// 512 thr = 16 warps: wm = wid&7 -> rows [wm*16,+16), wn = wid>>3 -> cols
// [wn*64,+64). acc = 32 regs/thread -> 2 CTAs/SM = 32 warps/SM (latency fix).
// ---------------------------------------------------------------------------
#define SMB 0
#define STG_STRIDE 132
#define SM_STG_BYTES (DN * STG_STRIDE * 4)     // 67584
#define SM_GEMM_TOTAL SM_STG_BYTES

template <bool RELU, bool IN16>
__global__ void __launch_bounds__(512, 2)
k_gemm_mma(const void* __restrict__ Ain, const __half* __restrict__ Bg,
           const float* __restrict__ dinv, __half* __restrict__ C, int n) {
    extern __shared__ __align__(16) char smem[];
    const uint32_t sbase = smem_to_u32(smem);
    const int tid = threadIdx.x;
    const int wid = tid >> 5;
    const int lane = tid & 31;
    const int wm = wid & 7;            // 8 m-warps of 16 rows
    const int wn = wid >> 3;           // 2 n-warps of 64 cols
    const int block_row = blockIdx.x * 128;

    // --- B copy (padded fp16, 34816 B) ---
    {
        const uint4* src = reinterpret_cast<const uint4*>(Bg);
        uint4* dst = reinterpret_cast<uint4*>(smem + SMB);
#pragma unroll
        for (int i = 0; i < 5; i++) {
            int f = tid + i * 512;
            if (f < DN * BPAD / 8) dst[f] = __ldg(&src[f]);
        }
    }

    const int r0 = block_row + wm * 16 + (lane >> 2);
    const int r1 = r0 + 8;
    const bool p0 = r0 < n;
    const bool p1 = r1 < n;
    const int coff = (lane & 3) * 2;

    __syncthreads();

    float acc[8][4];
#pragma unroll
    for (int jn = 0; jn < 8; jn++)
#pragma unroll
        for (int q = 0; q < 4; q++) acc[jn][q] = 0.f;

    const int lrow = lane & 15;
    const int lcol = (lane >> 4) << 3;

#pragma unroll
    for (int ks = 0; ks < 8; ks++) {
        const int k0 = ks * 16;
        uint32_t ah[4];
        if (IN16) {
            const __half* A = reinterpret_cast<const __half*>(Ain);
            const __half* A0 = A + (size_t)r0 * DN + coff;
            const __half* A1 = A + (size_t)r1 * DN + coff;
            __half2 z2 = __float2half2_rn(0.f);
            __half2 v0 = p0 ? *reinterpret_cast<const __half2*>(A0 + k0) : z2;
            __half2 v1 = p1 ? *reinterpret_cast<const __half2*>(A1 + k0) : z2;
            __half2 v2 = p0 ? *reinterpret_cast<const __half2*>(A0 + k0 + 8) : z2;
            __half2 v3 = p1 ? *reinterpret_cast<const __half2*>(A1 + k0 + 8) : z2;
            if (RELU) {
                v0 = __hmax2(v0, z2); v1 = __hmax2(v1, z2);
                v2 = __hmax2(v2, z2); v3 = __hmax2(v3, z2);
            }
            ah[0] = *reinterpret_cast<uint32_t*>(&v0);
            ah[1] = *reinterpret_cast<uint32_t*>(&v1);
            ah[2] = *reinterpret_cast<uint32_t*>(&v2);
            ah[3] = *reinterpret_cast<uint32_t*>(&v3);
        } else {
            const float* A = reinterpret_cast<const float*>(Ain);
            const float* A0 = A + (size_t)r0 * DN + coff;
            const float* A1 = A + (size_t)r1 * DN + coff;
            const float2 fz = make_float2(0.f, 0.f);
            float2 f00 = p0 ? *reinterpret_cast<const float2*>(A0 + k0) : fz;
            float2 f10 = p1 ? *reinterpret_cast<const float2*>(A1 + k0) : fz;
            float2 f01 = p0 ? *reinterpret_cast<const float2*>(A0 + k0 + 8) : fz;
            float2 f11 = p1 ? *reinterpret_cast<const float2*>(A1 + k0 + 8) : fz;
            if (RELU) {
                f00.x = fmaxf(f00.x, 0.f); f00.y = fmaxf(f00.y, 0.f);
                f10.x = fmaxf(f10.x, 0.f); f10.y = fmaxf(f10.y, 0.f);
                f01.x = fmaxf(f01.x, 0.f); f01.y = fmaxf(f01.y, 0.f);
                f11.x = fmaxf(f11.x, 0.f); f11.y = fmaxf(f11.y, 0.f);
            }
            __half2 h;
            h = __floats2half2_rn(f00.x, f00.y); ah[0] = *reinterpret_cast<uint32_t*>(&h);
            h = __floats2half2_rn(f10.x, f10.y); ah[1] = *reinterpret_cast<uint32_t*>(&h);
            h = __floats2half2_rn(f01.x, f01.y); ah[2] = *reinterpret_cast<uint32_t*>(&h);
            h = __floats2half2_rn(f11.x, f11.y); ah[3] = *reinterpret_cast<uint32_t*>(&h);
        }

#pragma unroll
        for (int jg = 0; jg < 4; jg++) {
            uint32_t bh[4];
            int colb = wn * 64 + jg * 16;
            uint32_t off = (uint32_t)(((colb + lrow) * BPAD + k0 + lcol) * 2);
            LDMATRIX_X4(bh, sbase + SMB + off);
            MMA_F16(acc[jg * 2],     ah, bh[0], bh[2]);
            MMA_F16(acc[jg * 2 + 1], ah, bh[1], bh[3]);
        }
    }
    __syncthreads();     // done reading B smem; reuse as fp32 staging

    // --- Epilogue: stage fp32, dinv-scale, coalesced fp16 store ---
    {
        float* stage = reinterpret_cast<float*>(smem);
        const int trow = lane >> 2;
        const int tcol = (lane & 3) * 2;
#pragma unroll
        for (int jn = 0; jn < 8; jn++) {
            int rr = wm * 16 + trow;
            int c = wn * 64 + jn * 8 + tcol;
            stage[rr * STG_STRIDE + c]     = acc[jn][0];
            stage[rr * STG_STRIDE + c + 1] = acc[jn][1];
            stage[(rr + 8) * STG_STRIDE + c]     = acc[jn][2];
            stage[(rr + 8) * STG_STRIDE + c + 1] = acc[jn][3];
        }
        __syncthreads();
        uint2* C2 = reinterpret_cast<uint2*>(C);
#pragma unroll
        for (int i = 0; i < 8; i++) {
            int f = tid + i * 512;                  // 4096 uint2
            int r = f >> 5;
            int c4 = f & 31;
            int gr = block_row + r;
            if (gr < n) {
                float s = __ldg(&dinv[gr]);
                const float* sp = &stage[r * STG_STRIDE + c4 * 4];
                __half2 a = __floats2half2_rn(s * sp[0], s * sp[1]);
                __half2 b = __floats2half2_rn(s * sp[2], s * sp[3]);
                C2[(size_t)gr * 32 + c4] =
                    make_uint2(*reinterpret_cast<uint32_t*>(&a),
                               *reinterpret_cast<uint32_t*>(&b));
            }
        }
    }
}

// ---------------------------------------------------------------------------
// Gather (no atomics): warp per target node c, h' = dinv-scaled fp16:
//   out[c] = dinv[c] * ( h'[c] + sum_r h'[r] ) + b
// ---------------------------------------------------------------------------
template <bool OUT16>
__global__ void __launch_bounds__(256)
k_gather(const __half* __restrict__ h, const float* __restrict__ dinv,
         const int* __restrict__ rowstart, const int* __restrict__ csr,
         const float* __restrict__ b, void* __restrict__ outp, int n) {
    int gid = blockIdx.x * blockDim.x + threadIdx.x;
    int node = gid >> 5;
    if (node >= n) return;
    int lane = gid & 31;

    const uint2* h2 = reinterpret_cast<const uint2*>(h);

    uint2 sv = __ldg(&h2[(size_t)node * 32 + lane]);
    float2 f01 = __half22float2(*reinterpret_cast<__half2*>(&sv.x));
    float2 f23 = __half22float2(*reinterpret_cast<__half2*>(&sv.y));
    float4 acc = make_float4(f01.x, f01.y, f23.x, f23.y);

    int s = __ldg(&rowstart[node]);
    int t = __ldg(&rowstart[node + 1]);
    int j = s;
    for (; j + 1 < t; j += 2) {
        int ra = __ldg(&csr[j]);
        int rb = __ldg(&csr[j + 1]);
        uint2 va = __ldg(&h2[(size_t)ra * 32 + lane]);
        uint2 vb = __ldg(&h2[(size_t)rb * 32 + lane]);
        float2 a01 = __half22float2(*reinterpret_cast<__half2*>(&va.x));
        float2 a23 = __half22float2(*reinterpret_cast<__half2*>(&va.y));
        float2 b01 = __half22float2(*reinterpret_cast<__half2*>(&vb.x));
        float2 b23 = __half22float2(*reinterpret_cast<__half2*>(&vb.y));
        acc.x += a01.x + b01.x;
        acc.y += a01.y + b01.y;
        acc.z += a23.x + b23.x;
        acc.w += a23.y + b23.y;
    }
    if (j < t) {
        int r = __ldg(&csr[j]);
        uint2 v = __ldg(&h2[(size_t)r * 32 + lane]);
        float2 g01 = __half22float2(*reinterpret_cast<__half2*>(&v.x));
        float2 g23 = __half22float2(*reinterpret_cast<__half2*>(&v.y));
        acc.x += g01.x; acc.y += g01.y;
        acc.z += g23.x; acc.w += g23.y;
    }

    float dc = __ldg(&dinv[node]);
    float4 bv = reinterpret_cast<const float4*>(b)[lane];
    float4 o;
    o.x = fmaf(dc, acc.x, bv.x);
    o.y = fmaf(dc, acc.y, bv.y);
    o.z = fmaf(dc, acc.z, bv.z);
    o.w = fmaf(dc, acc.w, bv.w);

    if (OUT16) {
        __half2 a = __floats2half2_rn(o.x, o.y);
        __half2 c = __floats2half2_rn(o.z, o.w);
        reinterpret_cast<uint2*>(outp)[(size_t)node * 32 + lane] =
            make_uint2(*reinterpret_cast<uint32_t*>(&a),
                       *reinterpret_cast<uint32_t*>(&c));
    } else {
        reinterpret_cast<float4*>(outp)[(size_t)node * 32 + lane] = o;
    }
}

// ---------------------------------------------------------------------------
extern "C" void kernel_launch(void* const* d_in, const int* in_sizes, int n_in,
                              void* d_out, int out_size) {
    const float* x  = (const float*)d_in[0];
    const int*   ei = (const int*)d_in[1];
    const float* W1 = (const float*)d_in[2];
    const float* b1 = (const float*)d_in[3];
    const float* W2 = (const float*)d_in[4];
    const float* b2 = (const float*)d_in[5];
    float* out = (float*)d_out;

    const int n = in_sizes[0] / DN;
    const int e = in_sizes[1] / 2;
    const int* rowv = ei;
    const int* colv = ei + e;

    int *degi, *part, *bsums, *rowstart, *cursor, *csr;
    float *dinv;
    __half *hbuf1, *hbuf2, *B;
    cudaGetSymbolAddress((void**)&degi, g_degi);
    cudaGetSymbolAddress((void**)&part, g_part);
    cudaGetSymbolAddress((void**)&bsums, g_bsums);
    cudaGetSymbolAddress((void**)&rowstart, g_rowstart);
    cudaGetSymbolAddress((void**)&cursor, g_cursor);
    cudaGetSymbolAddress((void**)&csr, g_csr);
    cudaGetSymbolAddress((void**)&dinv, g_dinv);
    cudaGetSymbolAddress((void**)&hbuf1, g_hbuf1);
    cudaGetSymbolAddress((void**)&hbuf2, g_hbuf2);
    cudaGetSymbolAddress((void**)&B, g_B);

    cudaFuncSetAttribute(k_gemm_mma<false, false>,
                         cudaFuncAttributeMaxDynamicSharedMemorySize, SM_GEMM_TOTAL);
    cudaFuncSetAttribute(k_gemm_mma<true, true>,
                         cudaFuncAttributeMaxDynamicSharedMemorySize, SM_GEMM_TOTAL);

    const int T = 256;
    const int nb = (n + T - 1) / T;
    const int eb = (e + T - 1) / T;
    const int eb4 = ((e + 3) / 4 + T - 1) / T;

    const int gemm_blocks = (n + 127) / 128;
    const int gather_blocks = (int)(((long long)n * 32 + T - 1) / T);

    k_wconv<<<(2 * DN * DN + T - 1) / T, T>>>(W1, W2, B);
    cudaMemsetAsync(degi, 0, n * sizeof(int));
    k_count_deg<<<eb4, T>>>(colv, degi, e);
    k_scan1<<<nb, T>>>(degi, part, bsums, n);
    k_scan3<<<nb, T>>>(part, bsums, degi, dinv, rowstart, cursor, n, e);

    // Layer-1 GEMM (needs dinv from scan3; not CSR)
    k_gemm_mma<false, false><<<gemm_blocks, 512, SM_GEMM_TOTAL>>>(x, B, dinv, hbuf1, n);

    // CSR fill (must precede gather-1)
    k_fill<<<eb, T>>>(rowv, colv, cursor, csr, e);

    k_gather<true><<<gather_blocks, T>>>(hbuf1, dinv, rowstart, csr, b1, hbuf2, n);
    // Layer 2
    k_gemm_mma<true, true><<<gemm_blocks, 512, SM_GEMM_TOTAL>>>(hbuf2, B + DN * BPAD,
                                                                dinv, hbuf1, n);
    k_gather<false><<<gather_blocks, T>>>(hbuf1, dinv, rowstart, csr, b2, out, n);
}

// round 16
// speedup vs baseline: 1.0705x; 1.0705x over previous
#include <cuda_runtime.h>
#include <cuda_fp16.h>
#include <cstdint>

#define DN 128
#define N_MAX 100000
#define E_MAX 2000000
#define BPAD 136                 // padded fp16 row stride (ldmatrix conflict-free)

// ---------------------------------------------------------------------------
// Scratch (__device__ globals; no allocation allowed)
// ---------------------------------------------------------------------------
__device__ int   g_degi[N_MAX];
__device__ int   g_part[N_MAX];
__device__ int   g_bsums[512];
__device__ int   g_rowstart[N_MAX + 1];
__device__ int   g_cursor[N_MAX];
__device__ int   g_csr[E_MAX];
__device__ float g_dinv[N_MAX];
// fp16 feature buffers (dinv-scaled h / agg), 128 halfs per node
__device__ __align__(16) __half g_hbuf1[(size_t)N_MAX * DN];
__device__ __align__(16) __half g_hbuf2[(size_t)N_MAX * DN];
// W transposed: B[n][k] = W[k][n], fp16, padded [n][BPAD]; 2 layers
__device__ __align__(16) __half g_B[2][DN * BPAD];

__device__ __forceinline__ uint32_t smem_to_u32(const void* p) {
    uint32_t addr;
    asm("{ .reg .u64 tmp; cvta.to.shared.u64 tmp, %1; cvt.u32.u64 %0, tmp; }"
        : "=r"(addr) : "l"(p));
    return addr;
}

#define LDMATRIX_X4(r, addr) \
    asm volatile("ldmatrix.sync.aligned.m8n8.x4.shared.b16 {%0,%1,%2,%3}, [%4];" \
                 : "=r"((r)[0]), "=r"((r)[1]), "=r"((r)[2]), "=r"((r)[3]) \
                 : "r"(addr))

#define MMA_F16(d, a, b0, b1) \
    asm volatile("mma.sync.aligned.m16n8k16.row.col.f32.f16.f16.f32 " \
                 "{%0,%1,%2,%3}, {%4,%5,%6,%7}, {%8,%9}, {%0,%1,%2,%3};" \
                 : "+f"((d)[0]), "+f"((d)[1]), "+f"((d)[2]), "+f"((d)[3]) \
                 : "r"((a)[0]), "r"((a)[1]), "r"((a)[2]), "r"((a)[3]), \
                   "r"(b0), "r"(b1))

// ---------------------------------------------------------------------------
// CSR build (by target/col node) + dinv  — exact R10 structure
// ---------------------------------------------------------------------------
__global__ void k_count_deg(const int* __restrict__ col, int* __restrict__ deg, int e) {
    int i = blockIdx.x * blockDim.x + threadIdx.x;
    int base = i * 4;
    if (base + 3 < e) {
        int4 c = *reinterpret_cast<const int4*>(col + base);
        atomicAdd(&deg[c.x], 1);
        atomicAdd(&deg[c.y], 1);
        atomicAdd(&deg[c.z], 1);
        atomicAdd(&deg[c.w], 1);
    } else {
        for (int j = base; j < e; j++) atomicAdd(&deg[col[j]], 1);
    }
}

__global__ void k_scan1(const int* __restrict__ deg, int* __restrict__ part,
                        int* __restrict__ bsums, int n) {
    __shared__ int sh[256];
    int t = threadIdx.x;
    int i = blockIdx.x * 256 + t;
    int v = (i < n) ? deg[i] : 0;
    sh[t] = v;
    __syncthreads();
#pragma unroll
    for (int off = 1; off < 256; off <<= 1) {
        int add = (t >= off) ? sh[t - off] : 0;
        __syncthreads();
        sh[t] += add;
        __syncthreads();
    }
    if (i < n) part[i] = sh[t] - v;
    if (t == 255) bsums[blockIdx.x] = sh[255];
}

__global__ void k_scan3(const int* __restrict__ part, const int* __restrict__ bsums,
                        const int* __restrict__ deg, float* __restrict__ dinv,
                        int* __restrict__ rowstart, int* __restrict__ cursor,
                        int n, int e) {
    __shared__ int sred[256];
    int t = threadIdx.x;
    int accum = 0;
    for (int j = t; j < (int)blockIdx.x; j += 256) accum += bsums[j];
    sred[t] = accum;
    __syncthreads();
#pragma unroll
    for (int off = 128; off > 0; off >>= 1) {
        if (t < off) sred[t] += sred[t + off];
        __syncthreads();
    }
    int base = sred[0];

    int i = blockIdx.x * 256 + t;
    if (i < n) {
        int v = part[i] + base;
        rowstart[i] = v;
        cursor[i] = v;
        dinv[i] = rsqrtf((float)deg[i] + 1.0f);
    }
    if (i == 0 && blockIdx.x == 0) rowstart[n] = e;
}

__global__ void k_fill(const int* __restrict__ rowv, const int* __restrict__ colv,
                       int* __restrict__ cursor, int* __restrict__ csr, int e) {
    int i = blockIdx.x * blockDim.x + threadIdx.x;
    if (i < e) {
        int pos = atomicAdd(&cursor[colv[i]], 1);
        csr[pos] = rowv[i];
    }
}

__global__ void k_wconv(const float* __restrict__ W1, const float* __restrict__ W2,
                        __half* __restrict__ B) {
    int gi = blockIdx.x * blockDim.x + threadIdx.x;
    if (gi >= 2 * DN * DN) return;
    int layer = gi >> 14;
    int i = gi & (DN * DN - 1);
    const float* W = layer ? W2 : W1;
    int nrow = i & 127;
    int k = i >> 7;
    B[layer * DN * BPAD + nrow * BPAD + k] = __float2half_rn(W[k * DN + nrow]);
}

// ---------------------------------------------------------------------------
// mma.sync GEMM: C_fp16[i,:] = dinv[i] * (act(A[i,:]) @ W)
// CTA tile 64 rows x 128 cols, 256 thr = 8 warps (4 m x 2 n), warp m16n64.
// acc = 32 regs/thread -> ~85 regs total -> 3 CTAs/SM = 24 warps (latency fix).
// Smem = B tile (34816 B); 64-row fp32 staging reuses it after MMA sync.
// ---------------------------------------------------------------------------
#define SMB 0
#define STG_STRIDE 132
#define SM_GEMM_TOTAL (DN * BPAD * 2)          // 34816 (> 64*132*4 = 33792)

template <bool RELU, bool IN16>
__global__ void __launch_bounds__(256, 3)
k_gemm_mma(const void* __restrict__ Ain, const __half* __restrict__ Bg,
           const float* __restrict__ dinv, __half* __restrict__ C, int n) {
    extern __shared__ __align__(16) char smem[];
    const uint32_t sbase = smem_to_u32(smem);
    const int tid = threadIdx.x;
    const int wid = tid >> 5;
    const int lane = tid & 31;
    const int wm = wid & 3;            // 4 m-warps of 16 rows (64 rows)
    const int wn = wid >> 2;           // 2 n-warps of 64 cols
    const int block_row = blockIdx.x * 64;

    // --- B copy (padded fp16, 34816 B) ---
    {
        const uint4* src = reinterpret_cast<const uint4*>(Bg);
        uint4* dst = reinterpret_cast<uint4*>(smem + SMB);
#pragma unroll
        for (int i = 0; i < 9; i++) {
            int f = tid + i * 256;
            if (f < DN * BPAD / 8) dst[f] = __ldg(&src[f]);
        }
    }

    const int r0 = block_row + wm * 16 + (lane >> 2);
    const int r1 = r0 + 8;
    const bool p0 = r0 < n;
    const bool p1 = r1 < n;
    const int coff = (lane & 3) * 2;

    __syncthreads();

    float acc[8][4];
#pragma unroll
    for (int jn = 0; jn < 8; jn++)
#pragma unroll
        for (int q = 0; q < 4; q++) acc[jn][q] = 0.f;

    const int lrow = lane & 15;
    const int lcol = (lane >> 4) << 3;

#pragma unroll
    for (int ks = 0; ks < 8; ks++) {
        const int k0 = ks * 16;
        uint32_t ah[4];
        if (IN16) {
            const __half* A = reinterpret_cast<const __half*>(Ain);
            const __half* A0 = A + (size_t)r0 * DN + coff;
            const __half* A1 = A + (size_t)r1 * DN + coff;
            __half2 z2 = __float2half2_rn(0.f);
            __half2 v0 = p0 ? *reinterpret_cast<const __half2*>(A0 + k0) : z2;
            __half2 v1 = p1 ? *reinterpret_cast<const __half2*>(A1 + k0) : z2;
            __half2 v2 = p0 ? *reinterpret_cast<const __half2*>(A0 + k0 + 8) : z2;
            __half2 v3 = p1 ? *reinterpret_cast<const __half2*>(A1 + k0 + 8) : z2;
            if (RELU) {
                v0 = __hmax2(v0, z2); v1 = __hmax2(v1, z2);
                v2 = __hmax2(v2, z2); v3 = __hmax2(v3, z2);
            }
            ah[0] = *reinterpret_cast<uint32_t*>(&v0);
            ah[1] = *reinterpret_cast<uint32_t*>(&v1);
            ah[2] = *reinterpret_cast<uint32_t*>(&v2);
            ah[3] = *reinterpret_cast<uint32_t*>(&v3);
        } else {
            const float* A = reinterpret_cast<const float*>(Ain);
            const float* A0 = A + (size_t)r0 * DN + coff;
            const float* A1 = A + (size_t)r1 * DN + coff;
            const float2 fz = make_float2(0.f, 0.f);
            float2 f00 = p0 ? *reinterpret_cast<const float2*>(A0 + k0) : fz;
            float2 f10 = p1 ? *reinterpret_cast<const float2*>(A1 + k0) : fz;
            float2 f01 = p0 ? *reinterpret_cast<const float2*>(A0 + k0 + 8) : fz;
            float2 f11 = p1 ? *reinterpret_cast<const float2*>(A1 + k0 + 8) : fz;
            if (RELU) {
                f00.x = fmaxf(f00.x, 0.f); f00.y = fmaxf(f00.y, 0.f);
                f10.x = fmaxf(f10.x, 0.f); f10.y = fmaxf(f10.y, 0.f);
                f01.x = fmaxf(f01.x, 0.f); f01.y = fmaxf(f01.y, 0.f);
                f11.x = fmaxf(f11.x, 0.f); f11.y = fmaxf(f11.y, 0.f);
            }
            __half2 h;
            h = __floats2half2_rn(f00.x, f00.y); ah[0] = *reinterpret_cast<uint32_t*>(&h);
            h = __floats2half2_rn(f10.x, f10.y); ah[1] = *reinterpret_cast<uint32_t*>(&h);
            h = __floats2half2_rn(f01.x, f01.y); ah[2] = *reinterpret_cast<uint32_t*>(&h);
            h = __floats2half2_rn(f11.x, f11.y); ah[3] = *reinterpret_cast<uint32_t*>(&h);
        }

#pragma unroll
        for (int jg = 0; jg < 4; jg++) {
            uint32_t bh[4];
            int colb = wn * 64 + jg * 16;
            uint32_t off = (uint32_t)(((colb + lrow) * BPAD + k0 + lcol) * 2);
            LDMATRIX_X4(bh, sbase + SMB + off);
            MMA_F16(acc[jg * 2],     ah, bh[0], bh[2]);
            MMA_F16(acc[jg * 2 + 1], ah, bh[1], bh[3]);
        }
    }
    __syncthreads();     // done reading B smem; reuse as fp32 staging (64 rows)

    // --- Epilogue: stage fp32, dinv-scale, coalesced fp16 store ---
    {
        float* stage = reinterpret_cast<float*>(smem);   // 64 x STG_STRIDE fp32
        const int trow = lane >> 2;
        const int tcol = (lane & 3) * 2;
#pragma unroll
        for (int jn = 0; jn < 8; jn++) {
            int rr = wm * 16 + trow;
            int c = wn * 64 + jn * 8 + tcol;
            stage[rr * STG_STRIDE + c]     = acc[jn][0];
            stage[rr * STG_STRIDE + c + 1] = acc[jn][1];
            stage[(rr + 8) * STG_STRIDE + c]     = acc[jn][2];
            stage[(rr + 8) * STG_STRIDE + c + 1] = acc[jn][3];
        }
        __syncthreads();
        uint2* C2 = reinterpret_cast<uint2*>(C);        // 4 halfs per uint2
#pragma unroll
        for (int i = 0; i < 8; i++) {
            int f = tid + i * 256;                      // 2048 uint2 (64 rows)
            int r = f >> 5;
            int c4 = f & 31;
            int gr = block_row + r;
            if (gr < n) {
                float s = __ldg(&dinv[gr]);
                const float* sp = &stage[r * STG_STRIDE + c4 * 4];
                __half2 a = __floats2half2_rn(s * sp[0], s * sp[1]);
                __half2 b = __floats2half2_rn(s * sp[2], s * sp[3]);
                C2[(size_t)gr * 32 + c4] =
                    make_uint2(*reinterpret_cast<uint32_t*>(&a),
                               *reinterpret_cast<uint32_t*>(&b));
            }
        }
    }
}

// ---------------------------------------------------------------------------
// Gather (no atomics): warp per target node c, h' = dinv-scaled fp16:
//   out[c] = dinv[c] * ( h'[c] + sum_r h'[r] ) + b
// ---------------------------------------------------------------------------
template <bool OUT16>
__global__ void __launch_bounds__(256)
k_gather(const __half* __restrict__ h, const float* __restrict__ dinv,
         const int* __restrict__ rowstart, const int* __restrict__ csr,
         const float* __restrict__ b, void* __restrict__ outp, int n) {
    int gid = blockIdx.x * blockDim.x + threadIdx.x;
    int node = gid >> 5;
    if (node >= n) return;
    int lane = gid & 31;

    const uint2* h2 = reinterpret_cast<const uint2*>(h);

    uint2 sv = __ldg(&h2[(size_t)node * 32 + lane]);
    float2 f01 = __half22float2(*reinterpret_cast<__half2*>(&sv.x));
    float2 f23 = __half22float2(*reinterpret_cast<__half2*>(&sv.y));
    float4 acc = make_float4(f01.x, f01.y, f23.x, f23.y);

    int s = __ldg(&rowstart[node]);
    int t = __ldg(&rowstart[node + 1]);
    int j = s;
    for (; j + 1 < t; j += 2) {
        int ra = __ldg(&csr[j]);
        int rb = __ldg(&csr[j + 1]);
        uint2 va = __ldg(&h2[(size_t)ra * 32 + lane]);
        uint2 vb = __ldg(&h2[(size_t)rb * 32 + lane]);
        float2 a01 = __half22float2(*reinterpret_cast<__half2*>(&va.x));
        float2 a23 = __half22float2(*reinterpret_cast<__half2*>(&va.y));
        float2 b01 = __half22float2(*reinterpret_cast<__half2*>(&vb.x));
        float2 b23 = __half22float2(*reinterpret_cast<__half2*>(&vb.y));
        acc.x += a01.x + b01.x;
        acc.y += a01.y + b01.y;
        acc.z += a23.x + b23.x;
        acc.w += a23.y + b23.y;
    }
    if (j < t) {
        int r = __ldg(&csr[j]);
        uint2 v = __ldg(&h2[(size_t)r * 32 + lane]);
        float2 g01 = __half22float2(*reinterpret_cast<__half2*>(&v.x));
        float2 g23 = __half22float2(*reinterpret_cast<__half2*>(&v.y));
        acc.x += g01.x; acc.y += g01.y;
        acc.z += g23.x; acc.w += g23.y;
    }

    float dc = __ldg(&dinv[node]);
    float4 bv = reinterpret_cast<const float4*>(b)[lane];
    float4 o;
    o.x = fmaf(dc, acc.x, bv.x);
    o.y = fmaf(dc, acc.y, bv.y);
    o.z = fmaf(dc, acc.z, bv.z);
    o.w = fmaf(dc, acc.w, bv.w);

    if (OUT16) {
        __half2 a = __floats2half2_rn(o.x, o.y);
        __half2 c = __floats2half2_rn(o.z, o.w);
        reinterpret_cast<uint2*>(outp)[(size_t)node * 32 + lane] =
            make_uint2(*reinterpret_cast<uint32_t*>(&a),
                       *reinterpret_cast<uint32_t*>(&c));
    } else {
        reinterpret_cast<float4*>(outp)[(size_t)node * 32 + lane] = o;
    }
}

// ---------------------------------------------------------------------------
extern "C" void kernel_launch(void* const* d_in, const int* in_sizes, int n_in,
                              void* d_out, int out_size) {
    const float* x  = (const float*)d_in[0];
    const int*   ei = (const int*)d_in[1];
    const float* W1 = (const float*)d_in[2];
    const float* b1 = (const float*)d_in[3];
    const float* W2 = (const float*)d_in[4];
    const float* b2 = (const float*)d_in[5];
    float* out = (float*)d_out;

    const int n = in_sizes[0] / DN;
    const int e = in_sizes[1] / 2;
    const int* rowv = ei;
    const int* colv = ei + e;

    int *degi, *part, *bsums, *rowstart, *cursor, *csr;
    float *dinv;
    __half *hbuf1, *hbuf2, *B;
    cudaGetSymbolAddress((void**)&degi, g_degi);
    cudaGetSymbolAddress((void**)&part, g_part);
    cudaGetSymbolAddress((void**)&bsums, g_bsums);
    cudaGetSymbolAddress((void**)&rowstart, g_rowstart);
    cudaGetSymbolAddress((void**)&cursor, g_cursor);
    cudaGetSymbolAddress((void**)&csr, g_csr);
    cudaGetSymbolAddress((void**)&dinv, g_dinv);
    cudaGetSymbolAddress((void**)&hbuf1, g_hbuf1);
    cudaGetSymbolAddress((void**)&hbuf2, g_hbuf2);
    cudaGetSymbolAddress((void**)&B, g_B);

    cudaFuncSetAttribute(k_gemm_mma<false, false>,
                         cudaFuncAttributeMaxDynamicSharedMemorySize, SM_GEMM_TOTAL);
    cudaFuncSetAttribute(k_gemm_mma<true, true>,
                         cudaFuncAttributeMaxDynamicSharedMemorySize, SM_GEMM_TOTAL);

    const int T = 256;
    const int nb = (n + T - 1) / T;
    const int eb = (e + T - 1) / T;
    const int eb4 = ((e + 3) / 4 + T - 1) / T;

    const int gemm_blocks = (n + 63) / 64;
    const int gather_blocks = (int)(((long long)n * 32 + T - 1) / T);

    k_wconv<<<(2 * DN * DN + T - 1) / T, T>>>(W1, W2, B);
    cudaMemsetAsync(degi, 0, n * sizeof(int));
    k_count_deg<<<eb4, T>>>(colv, degi, e);
    k_scan1<<<nb, T>>>(degi, part, bsums, n);
    k_scan3<<<nb, T>>>(part, bsums, degi, dinv, rowstart, cursor, n, e);

    // Layer-1 GEMM (needs dinv from scan3; not CSR)
    k_gemm_mma<false, false><<<gemm_blocks, T, SM_GEMM_TOTAL>>>(x, B, dinv, hbuf1, n);

    // CSR fill (must precede gather-1)
    k_fill<<<eb, T>>>(rowv, colv, cursor, csr, e);

    k_gather<true><<<gather_blocks, T>>>(hbuf1, dinv, rowstart, csr, b1, hbuf2, n);
    // Layer 2
    k_gemm_mma<true, true><<<gemm_blocks, T, SM_GEMM_TOTAL>>>(hbuf2, B + DN * BPAD,
                                                              dinv, hbuf1, n);
    k_gather<false><<<gather_blocks, T>>>(hbuf1, dinv, rowstart, csr, b2, out, n);
}